// round 3
// baseline (speedup 1.0000x reference)
#include <cuda_runtime.h>
#include <math.h>

// Scratch: packed per-pixel data. x channels (3) in float4, tangent (2) in float2.
// Fixed problem size: B=2, H=W=1024.
#define MAXPIX (2 * 1024 * 1024)
__device__ float4 g_xpack[MAXPIX];
__device__ float2 g_tpack[MAXPIX];

__global__ void pack_kernel(const float* __restrict__ x, const float* __restrict__ t,
                            int B, int C, int HW) {
    int i = blockIdx.x * blockDim.x + threadIdx.x;
    int total = B * HW;
    if (i >= total) return;
    int b = i / HW;
    int p = i - b * HW;
    const float* xb = x + (size_t)b * C * HW;
    float4 xp;
    xp.x = xb[p];
    xp.y = (C > 1) ? xb[p + HW] : 0.f;
    xp.z = (C > 2) ? xb[p + 2 * HW] : 0.f;
    xp.w = 0.f;
    g_xpack[i] = xp;
    const float* tb = t + (size_t)b * 2 * HW;
    g_tpack[i] = make_float2(tb[p], tb[p + HW]);
}

__global__ __launch_bounds__(256) void fas_kernel(const float* __restrict__ sg,
                                                  float* __restrict__ out,
                                                  int B, int C, int H, int W) {
    int xi = blockIdx.x * blockDim.x + threadIdx.x;
    int yi = blockIdx.y * blockDim.y + threadIdx.y;
    int b = blockIdx.z;
    if (xi >= W || yi >= H) return;
    int HW = H * W;
    const float4* __restrict__ xp = g_xpack + (size_t)b * HW;
    const float2* __restrict__ tp = g_tpack + (size_t)b * HW;

    float ffactor = fminf((float)H, (float)W) / 1024.0f;
    float sigma = sg[b] * ffactor;
    float halfw = 2.0f * sigma;
    float ts2 = 2.0f * sigma * sigma;
    float step = (float)(1.0 / (0.3333 * (double)ffactor));
    float invW = 1.0f / (float)W;
    float invH = 1.0f / (float)H;
    float fW = (float)W, fH = (float)H;

    int pidx = yi * W + xi;
    float p0x = ((float)xi + 0.5f) * invW;
    float p0y = ((float)yi + 0.5f) * invH;
    float2 t0 = tp[pidx];
    float4 xc = xp[pidx];

    float a0 = 0.f, a1 = 0.f, a2 = 0.f, ssum = 0.f;

#pragma unroll
    for (int d = 0; d < 2; ++d) {
        float vx = d ? -t0.x : t0.x;
        float vy = d ? -t0.y : t0.y;
        float px = p0x + vx * invW;
        float py = p0y + vy * invH;
        float r = step;
#pragma unroll 1
        for (int it = 0; it < 8; ++it) {
            // Once r >= half_width, k == 0 for every remaining step (r monotone),
            // so all later contributions are exactly zero in the reference too.
            if (!(r < halfw)) break;
            float k = expf(-(r * r) / ts2);
            float kk = (px >= 0.f && px < 1.f && py >= 0.f && py < 1.f) ? k : 0.f;

            float fx = px * fW - 0.5f;
            float fy = py * fH - 0.5f;
            float x0f = floorf(fx), y0f = floorf(fy);
            float wx = fx - x0f, wy = fy - y0f;
            int x0 = (int)x0f; x0 = x0 < 0 ? 0 : (x0 > W - 1 ? W - 1 : x0);
            int x1 = x0 + 1;   x1 = x1 > W - 1 ? W - 1 : x1;
            int y0 = (int)y0f; y0 = y0 < 0 ? 0 : (y0 > H - 1 ? H - 1 : y0);
            int y1 = y0 + 1;   y1 = y1 > H - 1 ? H - 1 : y1;
            int i00 = y0 * W + x0, i01 = y0 * W + x1;
            int i10 = y1 * W + x0, i11 = y1 * W + x1;

            float4 c00 = xp[i00], c01 = xp[i01], c10 = xp[i10], c11 = xp[i11];
            float2 s00 = tp[i00], s01 = tp[i01], s10 = tp[i10], s11 = tp[i11];

            float omwx = 1.f - wx, omwy = 1.f - wy;
            // x sample (3 channels), reference lerp ordering
            float top0 = c00.x * omwx + c01.x * wx;
            float bot0 = c10.x * omwx + c11.x * wx;
            float top1 = c00.y * omwx + c01.y * wx;
            float bot1 = c10.y * omwx + c11.y * wx;
            float top2 = c00.z * omwx + c01.z * wx;
            float bot2 = c10.z * omwx + c11.z * wx;
            a0 += kk * (top0 * omwy + bot0 * wy);
            a1 += kk * (top1 * omwy + bot1 * wy);
            a2 += kk * (top2 * omwy + bot2 * wy);
            ssum += kk;

            // tangent sample (2 channels)
            float ttx = (s00.x * omwx + s01.x * wx) * omwy + (s10.x * omwx + s11.x * wx) * wy;
            float tty = (s00.y * omwx + s01.y * wx) * omwy + (s10.y * omwx + s11.y * wx) * wy;
            float vt = vx * ttx + vy * tty;
            if (vt < 0.f) { ttx = -ttx; tty = -tty; }
            vx = ttx; vy = tty;
            px += vx * invW;
            py += vy * invH;
            r += step;
        }
    }

    float denom = 1.f + ssum;
    size_t ob = (size_t)b * C * HW;
    out[ob + pidx] = (xc.x + a0) / denom;
    if (C > 1) out[ob + HW + pidx] = (xc.y + a1) / denom;
    if (C > 2) out[ob + 2 * HW + pidx] = (xc.z + a2) / denom;
}

extern "C" void kernel_launch(void* const* d_in, const int* in_sizes, int n_in,
                              void* d_out, int out_size) {
    const float* x = (const float*)d_in[0];
    const float* t = (const float*)d_in[1];
    const float* s = (const float*)d_in[2];
    float* out = (float*)d_out;

    int B = in_sizes[2];                 // sigma has B elements
    int HW = (in_sizes[1] / B) / 2;      // tangent is [B,2,H,W]
    int C = in_sizes[0] / (B * HW);      // x is [B,C,H,W]
    int H = (int)(sqrt((double)HW) + 0.5);
    int W = HW / H;

    int total = B * HW;
    if (total > MAXPIX) return;  // scratch sized for the fixed problem

    pack_kernel<<<(total + 255) / 256, 256>>>(x, t, B, C, HW);

    dim3 blk(32, 8);
    dim3 grd((W + 31) / 32, (H + 7) / 8, B);
    fas_kernel<<<grd, blk>>>(s, out, B, C, H, W);
}